// round 11
// baseline (speedup 1.0000x reference)
#include <cuda_runtime.h>
#include <cuda_bf16.h>
#include <cstddef>

// Problem constants
#define NN    4096          // nodes
#define BB    4             // batch
#define CC    32            // channels
#define TT    12            // time
#define FF    1536          // BT*C features per node
#define DCAP  256           // per-row neighbor capacity (max degree ~120)

typedef unsigned long long ull;

// ---------------- scratch (device globals; no allocations allowed) ----------
__device__ float g_dinv[NN];
__device__ int   g_len [NN];
__device__ int   g_col [NN * DCAP];
__device__ int   g_off [NN * DCAP];                // byte offsets (precomputed)
__device__ float g_cf  [NN * DCAP];                // coefficients (precomputed)
__device__ float         g_h  [(size_t)NN * FF];   // fp32 master
__device__ float         g_t1 [(size_t)NN * FF];
__device__ __nv_bfloat16 g_hb [(size_t)NN * FF];   // bf16 gather shadows
__device__ __nv_bfloat16 g_t1b[(size_t)NN * FF];

// ---- f32x2 helpers ----------------------------------------------------------
__device__ __forceinline__ ull fpack(float x, float y) {
    ull r; asm("mov.b64 %0, {%1, %2};" : "=l"(r) : "f"(x), "f"(y)); return r;
}
__device__ __forceinline__ ull fdup(float x) {
    ull r; asm("mov.b64 %0, {%1, %1};" : "=l"(r) : "f"(x)); return r;
}
__device__ __forceinline__ void funpack(ull a, float& x, float& y) {
    asm("mov.b64 {%0, %1}, %2;" : "=f"(x), "=f"(y) : "l"(a));
}
__device__ __forceinline__ void ffma2(ull& a, ull v, ull c) {
    asm("fma.rn.f32x2 %0, %1, %2, %0;" : "+l"(a) : "l"(v), "l"(c));
}

// ---------------- K1: CSR build + degree, float4 + warp scan -----------------
__global__ void k_build(const float* __restrict__ adj) {
    int warp = threadIdx.x >> 5;
    int lane = threadIdx.x & 31;
    int m = blockIdx.x * 8 + warp;
    const float4* row4 = (const float4*)(adj + (size_t)m * NN);
    int* cl = g_col + m * DCAP;
    int base = 0;
    for (int j0 = 0; j0 < NN; j0 += 128) {
        float4 v = row4[(j0 >> 2) + lane];
        unsigned nib = (v.x != 0.f ? 1u : 0u) | (v.y != 0.f ? 2u : 0u)
                     | (v.z != 0.f ? 4u : 0u) | (v.w != 0.f ? 8u : 0u);
        int c = __popc(nib);
        int sc = c;                       // inclusive scan over lanes
        #pragma unroll
        for (int o = 1; o < 32; o <<= 1) {
            int tv = __shfl_up_sync(0xffffffffu, sc, o);
            if (lane >= o) sc += tv;
        }
        int pos = base + sc - c;          // exclusive prefix
        int jb = j0 + 4 * lane;
        if (nib & 1u) { if (pos < DCAP) cl[pos] = jb;     pos++; }
        if (nib & 2u) { if (pos < DCAP) cl[pos] = jb + 1; pos++; }
        if (nib & 4u) { if (pos < DCAP) cl[pos] = jb + 2; pos++; }
        if (nib & 8u) { if (pos < DCAP) cl[pos] = jb + 3; pos++; }
        base += __shfl_sync(0xffffffffu, sc, 31);
    }
    if (lane == 0) {
        g_len[m]  = base < DCAP ? base : DCAP;
        g_dinv[m] = (base > 0) ? rsqrtf((float)base) : 0.f;  // degree == nnz
    }
}

// ---------------- K1b: materialize {offset, coef} SoA arrays -----------------
__global__ void k_coef() {
    int m = blockIdx.x;
    int len = g_len[m];
    float dm = g_dinv[m];
    for (int i = threadIdx.x; i < len; i += 128) {
        int j = g_col[m * DCAP + i];
        g_off[m * DCAP + i] = j * (FF * 2);
        g_cf [m * DCAP + i] = dm * g_dinv[j];
    }
}

// ---------------- K2: transpose x[B,C,N,T] -> h[n][f] (fp32 + bf16) ----------
__global__ void k_transpose(const float* __restrict__ x) {
    __shared__ float sm[32][193];
    int n0 = blockIdx.x * 16;
    int b  = blockIdx.y;
    for (int idx = threadIdx.x; idx < 32 * 192; idx += 256) {
        int c = idx / 192, r = idx % 192;   // r = n_local*12 + t
        sm[c][r] = x[(((size_t)(b * 32 + c)) * NN + n0) * TT + r];
    }
    __syncthreads();
    // pairwise store: thread handles (nl, t, c2) -> channels 2*c2, 2*c2+1
    for (int idx = threadIdx.x; idx < 16 * 192; idx += 256) {
        int nl  = idx / 192;
        int rem = idx % 192;
        int t  = rem >> 4;
        int c2 = rem & 15;
        int r = nl * TT + t;
        float v0 = sm[2 * c2][r];
        float v1 = sm[2 * c2 + 1][r];
        size_t o = (size_t)(n0 + nl) * FF + (b * TT + t) * 32 + 2 * c2;
        *(float2*)(g_h + o) = make_float2(v0, v1);
        *(__nv_bfloat162*)(g_hb + o) = __float22bfloat162_rn(make_float2(v0, v1));
    }
}

// ---- packed bf16x2 gather-accumulate: 8 features via 8 PRMT + 4 FFMA2 -------
__device__ __forceinline__ void acc8x2(ull* A, uint4 v, ull cc) {
    asm volatile("{\n\t"
        ".reg .b32 lo, hi;\n\t"
        ".reg .b64 vv;\n\t"
        "prmt.b32 lo, %1, 0, 0x1044;\n\t"
        "prmt.b32 hi, %1, 0, 0x3244;\n\t"
        "mov.b64 vv, {lo, hi};\n\t"
        "fma.rn.f32x2 %0, vv, %2, %0;\n\t"
        "}" : "+l"(A[0]) : "r"(v.x), "l"(cc));
    asm volatile("{\n\t"
        ".reg .b32 lo, hi;\n\t"
        ".reg .b64 vv;\n\t"
        "prmt.b32 lo, %1, 0, 0x1044;\n\t"
        "prmt.b32 hi, %1, 0, 0x3244;\n\t"
        "mov.b64 vv, {lo, hi};\n\t"
        "fma.rn.f32x2 %0, vv, %2, %0;\n\t"
        "}" : "+l"(A[1]) : "r"(v.y), "l"(cc));
    asm volatile("{\n\t"
        ".reg .b32 lo, hi;\n\t"
        ".reg .b64 vv;\n\t"
        "prmt.b32 lo, %1, 0, 0x1044;\n\t"
        "prmt.b32 hi, %1, 0, 0x3244;\n\t"
        "mov.b64 vv, {lo, hi};\n\t"
        "fma.rn.f32x2 %0, vv, %2, %0;\n\t"
        "}" : "+l"(A[2]) : "r"(v.z), "l"(cc));
    asm volatile("{\n\t"
        ".reg .b32 lo, hi;\n\t"
        ".reg .b64 vv;\n\t"
        "prmt.b32 lo, %1, 0, 0x1044;\n\t"
        "prmt.b32 hi, %1, 0, 0x3244;\n\t"
        "mov.b64 vv, {lo, hi};\n\t"
        "fma.rn.f32x2 %0, vv, %2, %0;\n\t"
        "}" : "+l"(A[3]) : "r"(v.w), "l"(cc));
}

// ---- shared SpMM body: batch-of-4 loads, SoA smem entries -------------------
__device__ __forceinline__ void spmm_body(ull* A, const int* s_off,
                                          const float* s_cf, int len,
                                          const char* base) {
    int i = 0;
    for (; i + 4 <= len; i += 4) {
        int4   off = *(const int4*)  (s_off + i);   // one LDS.128: 4 offsets
        float4 cf  = *(const float4*)(s_cf  + i);   // one LDS.128: 4 coefs
        uint4 v0 = __ldg((const uint4*)(base + off.x));
        uint4 v1 = __ldg((const uint4*)(base + off.y));
        uint4 v2 = __ldg((const uint4*)(base + off.z));
        uint4 v3 = __ldg((const uint4*)(base + off.w));
        acc8x2(A, v0, fdup(cf.x));
        acc8x2(A, v1, fdup(cf.y));
        acc8x2(A, v2, fdup(cf.z));
        acc8x2(A, v3, fdup(cf.w));
    }
    for (; i < len; i++) {
        uint4 v = __ldg((const uint4*)(base + s_off[i]));
        acc8x2(A, v, fdup(s_cf[i]));
    }
}

// ---------------- K3: Tx1 = h - norm_adj * h (bf16 gather, f32x2 math) -------
__global__ void __launch_bounds__(192) k_spmm1() {
    int m   = blockIdx.x;
    int f0b = threadIdx.x * 16;            // byte offset of this thread's 8 bf16
    __shared__ int   s_off[DCAP];
    __shared__ float s_cf [DCAP];
    int len = g_len[m];
    for (int i = threadIdx.x; i < len; i += 192) {
        s_off[i] = g_off[m * DCAP + i];
        s_cf [i] = g_cf [m * DCAP + i];
    }
    __syncthreads();

    ull A[4] = {0ull, 0ull, 0ull, 0ull};
    spmm_body(A, s_off, s_cf, len, (const char*)g_hb + f0b);

    float acc[8];
    funpack(A[0], acc[0], acc[1]);
    funpack(A[1], acc[2], acc[3]);
    funpack(A[2], acc[4], acc[5]);
    funpack(A[3], acc[6], acc[7]);

    size_t fbase = (size_t)m * FF + threadIdx.x * 8;
    float4 h0 = *(const float4*)(g_h + fbase);
    float4 h1 = *(const float4*)(g_h + fbase + 4);
    float r[8];
    r[0] = h0.x - acc[0]; r[1] = h0.y - acc[1];
    r[2] = h0.z - acc[2]; r[3] = h0.w - acc[3];
    r[4] = h1.x - acc[4]; r[5] = h1.y - acc[5];
    r[6] = h1.z - acc[6]; r[7] = h1.w - acc[7];
    *(float4*)(g_t1 + fbase)     = make_float4(r[0], r[1], r[2], r[3]);
    *(float4*)(g_t1 + fbase + 4) = make_float4(r[4], r[5], r[6], r[7]);
    uint4 o;
    *(__nv_bfloat162*)&o.x = __float22bfloat162_rn(make_float2(r[0], r[1]));
    *(__nv_bfloat162*)&o.y = __float22bfloat162_rn(make_float2(r[2], r[3]));
    *(__nv_bfloat162*)&o.z = __float22bfloat162_rn(make_float2(r[4], r[5]));
    *(__nv_bfloat162*)&o.w = __float22bfloat162_rn(make_float2(r[6], r[7]));
    *(uint4*)(g_t1b + fbase) = o;
}

// ---------------- K4: fused Tx2 + output GEMM --------------------------------
// Phase 1 (gather): tx2 = 2*(t1 - A*t1) - h  (kept in regs, staged to smem)
// Phase 2 (GEMM):   out[b][co][m][t] = h*W0 + t1*W1 + tx2*W2 + bias
//   thread (s = tid/4, q = tid&3): slot s -> (b = s/12, t = s%12), co in [8q, 8q+8)
__global__ void __launch_bounds__(192) k_spmm2_out(const float* __restrict__ w,
                                                   const float* __restrict__ bias,
                                                   float* __restrict__ out) {
    int m   = blockIdx.x;
    int tid = threadIdx.x;
    int f0b = tid * 16;
    __shared__ int   s_off[DCAP];
    __shared__ float s_cf [DCAP];
    __shared__ float sW[3 * 32 * 32];      // [k][c][co]
    __shared__ float sB[32];
    __shared__ float s_f[3][FF];           // h, t1, tx2 rows
    int len = g_len[m];
    for (int i = tid; i < len; i += 192) {
        s_off[i] = g_off[m * DCAP + i];
        s_cf [i] = g_cf [m * DCAP + i];
    }
    for (int idx = tid; idx < 3 * 32 * 32; idx += 192) sW[idx] = w[idx];
    if (tid < 32) sB[tid] = bias[tid];
    __syncthreads();

    ull A[4] = {0ull, 0ull, 0ull, 0ull};
    spmm_body(A, s_off, s_cf, len, (const char*)g_t1b + f0b);

    float acc[8];
    funpack(A[0], acc[0], acc[1]);
    funpack(A[1], acc[2], acc[3]);
    funpack(A[2], acc[4], acc[5]);
    funpack(A[3], acc[6], acc[7]);

    size_t fbase = (size_t)m * FF + tid * 8;
    float4 t0 = *(const float4*)(g_t1 + fbase);
    float4 t1 = *(const float4*)(g_t1 + fbase + 4);
    float4 h0 = *(const float4*)(g_h  + fbase);
    float4 h1 = *(const float4*)(g_h  + fbase + 4);
    float4 r0, r1;
    r0.x = 2.f * (t0.x - acc[0]) - h0.x;
    r0.y = 2.f * (t0.y - acc[1]) - h0.y;
    r0.z = 2.f * (t0.z - acc[2]) - h0.z;
    r0.w = 2.f * (t0.w - acc[3]) - h0.w;
    r1.x = 2.f * (t1.x - acc[4]) - h1.x;
    r1.y = 2.f * (t1.y - acc[5]) - h1.y;
    r1.z = 2.f * (t1.z - acc[6]) - h1.z;
    r1.w = 2.f * (t1.w - acc[7]) - h1.w;

    int f0 = tid * 8;
    *(float4*)&s_f[0][f0]     = h0;  *(float4*)&s_f[0][f0 + 4] = h1;
    *(float4*)&s_f[1][f0]     = t0;  *(float4*)&s_f[1][f0 + 4] = t1;
    *(float4*)&s_f[2][f0]     = r0;  *(float4*)&s_f[2][f0 + 4] = r1;
    __syncthreads();

    // ---- GEMM phase ----
    int s   = tid >> 2;
    int q   = tid & 3;
    int b   = s / 12, t = s % 12;
    int cob = q * 8;

    ull Ac[4];
    #pragma unroll
    for (int j = 0; j < 4; j++) Ac[j] = fpack(sB[cob + 2*j], sB[cob + 2*j + 1]);

    const float* f0p = &s_f[0][s * 32];
    const float* f1p = &s_f[1][s * 32];
    const float* f2p = &s_f[2][s * 32];

    #pragma unroll
    for (int c4 = 0; c4 < 8; c4++) {
        float4 X0 = *(const float4*)(f0p + c4 * 4);
        float4 X1 = *(const float4*)(f1p + c4 * 4);
        float4 X2 = *(const float4*)(f2p + c4 * 4);
        #pragma unroll
        for (int cc = 0; cc < 4; cc++) {
            int c = c4 * 4 + cc;
            ull a0 = fdup(((const float*)&X0)[cc]);
            ull a1 = fdup(((const float*)&X1)[cc]);
            ull a2 = fdup(((const float*)&X2)[cc]);
            const ulonglong2* w0 = (const ulonglong2*)(sW +            c * 32 + cob);
            const ulonglong2* w1 = (const ulonglong2*)(sW + 1024 +     c * 32 + cob);
            const ulonglong2* w2 = (const ulonglong2*)(sW + 2048 +     c * 32 + cob);
            ulonglong2 W0a = w0[0], W0b = w0[1];
            ulonglong2 W1a = w1[0], W1b = w1[1];
            ulonglong2 W2a = w2[0], W2b = w2[1];
            ffma2(Ac[0], W0a.x, a0); ffma2(Ac[1], W0a.y, a0);
            ffma2(Ac[2], W0b.x, a0); ffma2(Ac[3], W0b.y, a0);
            ffma2(Ac[0], W1a.x, a1); ffma2(Ac[1], W1a.y, a1);
            ffma2(Ac[2], W1b.x, a1); ffma2(Ac[3], W1b.y, a1);
            ffma2(Ac[0], W2a.x, a2); ffma2(Ac[1], W2a.y, a2);
            ffma2(Ac[2], W2b.x, a2); ffma2(Ac[3], W2b.y, a2);
        }
    }
    // out[b][co][m][t]
    float* po = out + (((size_t)(b * 32 + cob)) * NN + m) * TT + t;
    #pragma unroll
    for (int j = 0; j < 4; j++) {
        float x, y;
        funpack(Ac[j], x, y);
        po[(size_t)(2*j)     * NN * TT] = x;
        po[(size_t)(2*j + 1) * NN * TT] = y;
    }
}

// ---------------- launch -----------------------------------------------------
extern "C" void kernel_launch(void* const* d_in, const int* in_sizes, int n_in,
                              void* d_out, int out_size) {
    const float* x    = (const float*)d_in[0];   // [4,32,4096,12]
    const float* adj  = (const float*)d_in[1];   // [4096,4096]
    const float* w    = (const float*)d_in[2];   // [3,32,32]
    const float* bias = (const float*)d_in[3];   // [32]
    float* out = (float*)d_out;                  // [4,32,4096,12]

    k_build    <<<NN / 8, 256>>>(adj);
    k_coef     <<<NN, 128>>>();
    k_transpose<<<dim3(NN / 16, BB), 256>>>(x);
    k_spmm1    <<<NN, 192>>>();
    k_spmm2_out<<<NN, 192>>>(w, bias, out);
}

// round 12
// speedup vs baseline: 1.1989x; 1.1989x over previous
#include <cuda_runtime.h>
#include <cuda_bf16.h>
#include <cstddef>

// Problem constants
#define NN    4096          // nodes
#define BB    4             // batch
#define CC    32            // channels
#define TT    12            // time
#define FF    1536          // BT*C features per node
#define DCAP  256           // per-row neighbor capacity (max degree ~120)

typedef unsigned long long ull;

// ---------------- scratch (device globals; no allocations allowed) ----------
__device__ float g_dinv[NN];
__device__ int   g_len [NN];
__device__ int   g_col [NN * DCAP];
__device__ int   g_off [NN * DCAP];                // byte offsets (precomputed)
__device__ float g_cf  [NN * DCAP];                // coefficients (precomputed)
__device__ float         g_h  [(size_t)NN * FF];   // fp32 master
__device__ float         g_t1 [(size_t)NN * FF];
__device__ float         g_tx2[(size_t)NN * FF];
__device__ __nv_bfloat16 g_hb [(size_t)NN * FF];   // bf16 gather shadows
__device__ __nv_bfloat16 g_t1b[(size_t)NN * FF];

// ---- f32x2 helpers ----------------------------------------------------------
__device__ __forceinline__ ull fpack(float x, float y) {
    ull r; asm("mov.b64 %0, {%1, %2};" : "=l"(r) : "f"(x), "f"(y)); return r;
}
__device__ __forceinline__ ull fdup(float x) {
    ull r; asm("mov.b64 %0, {%1, %1};" : "=l"(r) : "f"(x)); return r;
}
__device__ __forceinline__ void funpack(ull a, float& x, float& y) {
    asm("mov.b64 {%0, %1}, %2;" : "=f"(x), "=f"(y) : "l"(a));
}
__device__ __forceinline__ void ffma2(ull& a, ull v, ull c) {
    asm("fma.rn.f32x2 %0, %1, %2, %0;" : "+l"(a) : "l"(v), "l"(c));
}

// ---------------- K1: CSR build + degree, float4 + warp scan -----------------
__global__ void k_build(const float* __restrict__ adj) {
    int warp = threadIdx.x >> 5;
    int lane = threadIdx.x & 31;
    int m = blockIdx.x * 8 + warp;
    const float4* row4 = (const float4*)(adj + (size_t)m * NN);
    int* cl = g_col + m * DCAP;
    int base = 0;
    for (int j0 = 0; j0 < NN; j0 += 128) {
        float4 v = row4[(j0 >> 2) + lane];
        unsigned nib = (v.x != 0.f ? 1u : 0u) | (v.y != 0.f ? 2u : 0u)
                     | (v.z != 0.f ? 4u : 0u) | (v.w != 0.f ? 8u : 0u);
        int c = __popc(nib);
        int sc = c;                       // inclusive scan over lanes
        #pragma unroll
        for (int o = 1; o < 32; o <<= 1) {
            int tv = __shfl_up_sync(0xffffffffu, sc, o);
            if (lane >= o) sc += tv;
        }
        int pos = base + sc - c;          // exclusive prefix
        int jb = j0 + 4 * lane;
        if (nib & 1u) { if (pos < DCAP) cl[pos] = jb;     pos++; }
        if (nib & 2u) { if (pos < DCAP) cl[pos] = jb + 1; pos++; }
        if (nib & 4u) { if (pos < DCAP) cl[pos] = jb + 2; pos++; }
        if (nib & 8u) { if (pos < DCAP) cl[pos] = jb + 3; pos++; }
        base += __shfl_sync(0xffffffffu, sc, 31);
    }
    if (lane == 0) {
        g_len[m]  = base < DCAP ? base : DCAP;
        g_dinv[m] = (base > 0) ? rsqrtf((float)base) : 0.f;  // degree == nnz
    }
}

// ---------------- K2: fused transpose + coef materialization -----------------
// blocks [0, 1024): transpose x[B,C,N,T] -> h[n][f] (fp32 + bf16 shadow)
// blocks [1024, 3072): 2 rows each: g_off/g_cf = {j*FF*2, dinv[m]*dinv[j]}
__global__ void k_prep(const float* __restrict__ x) {
    __shared__ float sm[32][193];
    if (blockIdx.x < 1024) {
        int n0 = (blockIdx.x & 255) * 16;
        int b  = blockIdx.x >> 8;
        for (int idx = threadIdx.x; idx < 32 * 192; idx += 256) {
            int c = idx / 192, r = idx % 192;   // r = n_local*12 + t
            sm[c][r] = x[(((size_t)(b * 32 + c)) * NN + n0) * TT + r];
        }
        __syncthreads();
        // pairwise store: thread handles (nl, t, c2) -> channels 2*c2, 2*c2+1
        for (int idx = threadIdx.x; idx < 16 * 192; idx += 256) {
            int nl  = idx / 192;
            int rem = idx % 192;
            int t  = rem >> 4;
            int c2 = rem & 15;
            int r = nl * TT + t;
            float v0 = sm[2 * c2][r];
            float v1 = sm[2 * c2 + 1][r];
            size_t o = (size_t)(n0 + nl) * FF + (b * TT + t) * 32 + 2 * c2;
            *(float2*)(g_h + o) = make_float2(v0, v1);
            *(__nv_bfloat162*)(g_hb + o) =
                __float22bfloat162_rn(make_float2(v0, v1));
        }
    } else {
        int idx = blockIdx.x - 1024;              // 0..2047
        int m   = idx * 2 + (threadIdx.x >> 7);   // half-block per row
        int tid = threadIdx.x & 127;
        int len = g_len[m];
        float dm = g_dinv[m];
        for (int i = tid; i < len; i += 128) {
            int j = g_col[m * DCAP + i];
            g_off[m * DCAP + i] = j * (FF * 2);
            g_cf [m * DCAP + i] = dm * g_dinv[j];
        }
    }
}

// ---- packed bf16x2 gather-accumulate: 8 features via 8 PRMT + 4 FFMA2 -------
__device__ __forceinline__ void acc8x2(ull* A, uint4 v, ull cc) {
    asm volatile("{\n\t"
        ".reg .b32 lo, hi;\n\t"
        ".reg .b64 vv;\n\t"
        "prmt.b32 lo, %1, 0, 0x1044;\n\t"
        "prmt.b32 hi, %1, 0, 0x3244;\n\t"
        "mov.b64 vv, {lo, hi};\n\t"
        "fma.rn.f32x2 %0, vv, %2, %0;\n\t"
        "}" : "+l"(A[0]) : "r"(v.x), "l"(cc));
    asm volatile("{\n\t"
        ".reg .b32 lo, hi;\n\t"
        ".reg .b64 vv;\n\t"
        "prmt.b32 lo, %1, 0, 0x1044;\n\t"
        "prmt.b32 hi, %1, 0, 0x3244;\n\t"
        "mov.b64 vv, {lo, hi};\n\t"
        "fma.rn.f32x2 %0, vv, %2, %0;\n\t"
        "}" : "+l"(A[1]) : "r"(v.y), "l"(cc));
    asm volatile("{\n\t"
        ".reg .b32 lo, hi;\n\t"
        ".reg .b64 vv;\n\t"
        "prmt.b32 lo, %1, 0, 0x1044;\n\t"
        "prmt.b32 hi, %1, 0, 0x3244;\n\t"
        "mov.b64 vv, {lo, hi};\n\t"
        "fma.rn.f32x2 %0, vv, %2, %0;\n\t"
        "}" : "+l"(A[2]) : "r"(v.z), "l"(cc));
    asm volatile("{\n\t"
        ".reg .b32 lo, hi;\n\t"
        ".reg .b64 vv;\n\t"
        "prmt.b32 lo, %1, 0, 0x1044;\n\t"
        "prmt.b32 hi, %1, 0, 0x3244;\n\t"
        "mov.b64 vv, {lo, hi};\n\t"
        "fma.rn.f32x2 %0, vv, %2, %0;\n\t"
        "}" : "+l"(A[3]) : "r"(v.w), "l"(cc));
}

// ---- shared SpMM body: batch-of-4 loads, SoA smem entries -------------------
__device__ __forceinline__ void spmm_body(ull* A, const int* s_off,
                                          const float* s_cf, int len,
                                          const char* base) {
    int i = 0;
    for (; i + 4 <= len; i += 4) {
        int4   off = *(const int4*)  (s_off + i);   // one LDS.128: 4 offsets
        float4 cf  = *(const float4*)(s_cf  + i);   // one LDS.128: 4 coefs
        uint4 v0 = __ldg((const uint4*)(base + off.x));
        uint4 v1 = __ldg((const uint4*)(base + off.y));
        uint4 v2 = __ldg((const uint4*)(base + off.z));
        uint4 v3 = __ldg((const uint4*)(base + off.w));
        acc8x2(A, v0, fdup(cf.x));
        acc8x2(A, v1, fdup(cf.y));
        acc8x2(A, v2, fdup(cf.z));
        acc8x2(A, v3, fdup(cf.w));
    }
    for (; i < len; i++) {
        uint4 v = __ldg((const uint4*)(base + s_off[i]));
        acc8x2(A, v, fdup(s_cf[i]));
    }
}

// ---------------- K3: Tx1 = h - norm_adj * h (bf16 gather, f32x2 math) -------
__global__ void __launch_bounds__(192) k_spmm1() {
    int m   = blockIdx.x;
    int f0b = threadIdx.x * 16;            // byte offset of this thread's 8 bf16
    __shared__ int   s_off[DCAP];
    __shared__ float s_cf [DCAP];
    int len = g_len[m];
    for (int i = threadIdx.x; i < len; i += 192) {
        s_off[i] = g_off[m * DCAP + i];
        s_cf [i] = g_cf [m * DCAP + i];
    }
    __syncthreads();

    ull A[4] = {0ull, 0ull, 0ull, 0ull};
    spmm_body(A, s_off, s_cf, len, (const char*)g_hb + f0b);

    float acc[8];
    funpack(A[0], acc[0], acc[1]);
    funpack(A[1], acc[2], acc[3]);
    funpack(A[2], acc[4], acc[5]);
    funpack(A[3], acc[6], acc[7]);

    size_t fbase = (size_t)m * FF + threadIdx.x * 8;
    float4 h0 = *(const float4*)(g_h + fbase);
    float4 h1 = *(const float4*)(g_h + fbase + 4);
    float r[8];
    r[0] = h0.x - acc[0]; r[1] = h0.y - acc[1];
    r[2] = h0.z - acc[2]; r[3] = h0.w - acc[3];
    r[4] = h1.x - acc[4]; r[5] = h1.y - acc[5];
    r[6] = h1.z - acc[6]; r[7] = h1.w - acc[7];
    *(float4*)(g_t1 + fbase)     = make_float4(r[0], r[1], r[2], r[3]);
    *(float4*)(g_t1 + fbase + 4) = make_float4(r[4], r[5], r[6], r[7]);
    uint4 o;
    *(__nv_bfloat162*)&o.x = __float22bfloat162_rn(make_float2(r[0], r[1]));
    *(__nv_bfloat162*)&o.y = __float22bfloat162_rn(make_float2(r[2], r[3]));
    *(__nv_bfloat162*)&o.z = __float22bfloat162_rn(make_float2(r[4], r[5]));
    *(__nv_bfloat162*)&o.w = __float22bfloat162_rn(make_float2(r[6], r[7]));
    *(uint4*)(g_t1b + fbase) = o;
}

// ---------------- K4: Tx2 = 2*(Tx1 - norm_adj*Tx1) - h -----------------------
__global__ void __launch_bounds__(192) k_spmm2() {
    int m   = blockIdx.x;
    int f0b = threadIdx.x * 16;
    __shared__ int   s_off[DCAP];
    __shared__ float s_cf [DCAP];
    int len = g_len[m];
    for (int i = threadIdx.x; i < len; i += 192) {
        s_off[i] = g_off[m * DCAP + i];
        s_cf [i] = g_cf [m * DCAP + i];
    }
    __syncthreads();

    ull A[4] = {0ull, 0ull, 0ull, 0ull};
    spmm_body(A, s_off, s_cf, len, (const char*)g_t1b + f0b);

    float acc[8];
    funpack(A[0], acc[0], acc[1]);
    funpack(A[1], acc[2], acc[3]);
    funpack(A[2], acc[4], acc[5]);
    funpack(A[3], acc[6], acc[7]);

    size_t fbase = (size_t)m * FF + threadIdx.x * 8;
    float4 t0 = *(const float4*)(g_t1 + fbase);
    float4 t1 = *(const float4*)(g_t1 + fbase + 4);
    float4 h0 = *(const float4*)(g_h  + fbase);
    float4 h1 = *(const float4*)(g_h  + fbase + 4);
    float4 r0, r1;
    r0.x = 2.f * (t0.x - acc[0]) - h0.x;
    r0.y = 2.f * (t0.y - acc[1]) - h0.y;
    r0.z = 2.f * (t0.z - acc[2]) - h0.z;
    r0.w = 2.f * (t0.w - acc[3]) - h0.w;
    r1.x = 2.f * (t1.x - acc[4]) - h1.x;
    r1.y = 2.f * (t1.y - acc[5]) - h1.y;
    r1.z = 2.f * (t1.z - acc[6]) - h1.z;
    r1.w = 2.f * (t1.w - acc[7]) - h1.w;
    *(float4*)(g_tx2 + fbase)     = r0;
    *(float4*)(g_tx2 + fbase + 4) = r1;
}

// ---------------- K5: out GEMM, 2 rows per thread (amortize weight LDS) ------
__global__ void __launch_bounds__(192) k_out(const float* __restrict__ w,
                                             const float* __restrict__ bias,
                                             float* __restrict__ out) {
    __shared__ float sW[3 * 32 * 32];   // [k][c][co]
    __shared__ float sB[32];
    for (int idx = threadIdx.x; idx < 3 * 32 * 32; idx += 192) sW[idx] = w[idx];
    if (threadIdx.x < 32) sB[threadIdx.x] = bias[threadIdx.x];
    __syncthreads();

    int b  = blockIdx.y;
    int p0 = threadIdx.x;          // row 0: (n,t) pair index
    int p1 = threadIdx.x + 192;    // row 1
    int n0b = blockIdx.x * 32;
    int na = n0b + p0 / 12, ta = p0 % 12;
    int nb = n0b + p1 / 12, tb = p1 % 12;

    size_t fba = (size_t)na * FF + (b * TT + ta) * 32;
    size_t fbb = (size_t)nb * FF + (b * TT + tb) * 32;

    ull Aa[16], Ab[16];            // 2 x 32 co accumulators as f32x2
    #pragma unroll
    for (int q = 0; q < 16; q++) {
        ull bq = fpack(sB[2*q], sB[2*q+1]);
        Aa[q] = bq; Ab[q] = bq;
    }

    #pragma unroll
    for (int c4 = 0; c4 < 8; c4++) {
        float4 Xa0 = __ldg((const float4*)(g_h   + fba + c4 * 4));
        float4 Xa1 = __ldg((const float4*)(g_t1  + fba + c4 * 4));
        float4 Xa2 = __ldg((const float4*)(g_tx2 + fba + c4 * 4));
        float4 Xb0 = __ldg((const float4*)(g_h   + fbb + c4 * 4));
        float4 Xb1 = __ldg((const float4*)(g_t1  + fbb + c4 * 4));
        float4 Xb2 = __ldg((const float4*)(g_tx2 + fbb + c4 * 4));
        #pragma unroll
        for (int cc = 0; cc < 4; cc++) {
            int c = c4 * 4 + cc;
            ull a0 = fdup(((const float*)&Xa0)[cc]);
            ull a1 = fdup(((const float*)&Xa1)[cc]);
            ull a2 = fdup(((const float*)&Xa2)[cc]);
            ull b0 = fdup(((const float*)&Xb0)[cc]);
            ull b1 = fdup(((const float*)&Xb1)[cc]);
            ull b2 = fdup(((const float*)&Xb2)[cc]);
            const ulonglong2* w0 = (const ulonglong2*)(sW +            c * 32);
            const ulonglong2* w1 = (const ulonglong2*)(sW + 32 * 32 +  c * 32);
            const ulonglong2* w2 = (const ulonglong2*)(sW + 2*32*32 +  c * 32);
            #pragma unroll
            for (int q = 0; q < 8; q++) {
                ulonglong2 W0 = w0[q], W1 = w1[q], W2 = w2[q];
                ffma2(Aa[2*q],   W0.x, a0); ffma2(Aa[2*q+1], W0.y, a0);
                ffma2(Aa[2*q],   W1.x, a1); ffma2(Aa[2*q+1], W1.y, a1);
                ffma2(Aa[2*q],   W2.x, a2); ffma2(Aa[2*q+1], W2.y, a2);
                ffma2(Ab[2*q],   W0.x, b0); ffma2(Ab[2*q+1], W0.y, b0);
                ffma2(Ab[2*q],   W1.x, b1); ffma2(Ab[2*q+1], W1.y, b1);
                ffma2(Ab[2*q],   W2.x, b2); ffma2(Ab[2*q+1], W2.y, b2);
            }
        }
    }
    float* poa = out + ((size_t)(b * 32) * NN + na) * TT + ta;
    float* pob = out + ((size_t)(b * 32) * NN + nb) * TT + tb;
    #pragma unroll
    for (int q = 0; q < 16; q++) {
        float x, y;
        funpack(Aa[q], x, y);
        poa[(size_t)(2*q)     * NN * TT] = x;
        poa[(size_t)(2*q + 1) * NN * TT] = y;
        funpack(Ab[q], x, y);
        pob[(size_t)(2*q)     * NN * TT] = x;
        pob[(size_t)(2*q + 1) * NN * TT] = y;
    }
}

// ---------------- launch -----------------------------------------------------
extern "C" void kernel_launch(void* const* d_in, const int* in_sizes, int n_in,
                              void* d_out, int out_size) {
    const float* x    = (const float*)d_in[0];   // [4,32,4096,12]
    const float* adj  = (const float*)d_in[1];   // [4096,4096]
    const float* w    = (const float*)d_in[2];   // [3,32,32]
    const float* bias = (const float*)d_in[3];   // [32]
    float* out = (float*)d_out;                  // [4,32,4096,12]

    k_build <<<NN / 8, 256>>>(adj);
    k_prep  <<<1024 + NN / 2, 256>>>(x);
    k_spmm1 <<<NN, 192>>>();
    k_spmm2 <<<NN, 192>>>();
    k_out   <<<dim3(NN / 32, BB), 192>>>(w, bias, out);
}

// round 13
// speedup vs baseline: 1.2107x; 1.0098x over previous
#include <cuda_runtime.h>
#include <cuda_bf16.h>
#include <cstddef>

// Problem constants
#define NN    4096          // nodes
#define BB    4             // batch
#define CC    32            // channels
#define TT    12            // time
#define FF    1536          // BT*C features per node
#define DCAP  256           // per-row neighbor capacity (max degree ~120)

typedef unsigned long long ull;

// ---------------- scratch (device globals; no allocations allowed) ----------
__device__ float g_dinv[NN];
__device__ int   g_len [NN];
__device__ int   g_col [NN * DCAP];
__device__ int   g_off [NN * DCAP];                // byte offsets (precomputed)
__device__ float g_cf  [NN * DCAP];                // coefficients (precomputed)
__device__ float         g_h  [(size_t)NN * FF];   // fp32 master
__device__ float         g_t1 [(size_t)NN * FF];
__device__ float         g_tx2[(size_t)NN * FF];
__device__ unsigned      g_hb [(size_t)NN * FF / 2];  // packed lattice-bf16 pairs
__device__ unsigned      g_t1b[(size_t)NN * FF / 2];

// ---- f32x2 helpers ----------------------------------------------------------
__device__ __forceinline__ ull fpack(float x, float y) {
    ull r; asm("mov.b64 %0, {%1, %2};" : "=l"(r) : "f"(x), "f"(y)); return r;
}
__device__ __forceinline__ ull fdup(float x) {
    ull r; asm("mov.b64 %0, {%1, %1};" : "=l"(r) : "f"(x)); return r;
}
__device__ __forceinline__ void funpack(ull a, float& x, float& y) {
    asm("mov.b64 {%0, %1}, %2;" : "=f"(x), "=f"(y) : "l"(a));
}
__device__ __forceinline__ void ffma2(ull& a, ull v, ull c) {
    asm("fma.rn.f32x2 %0, %1, %2, %0;" : "+l"(a) : "l"(v), "l"(c));
}

// ---- lattice pair encode -----------------------------------------------------
// word = (t<<16)|lo where lo = bf16_rn(v0) bits, t chosen so the whole word,
// read as fp32, is the nearest lattice point to v1 (error <= 2^-8 rel, same
// as bf16 rounding). Decode: v0 = prmt-shift (exact bf16), v1 = raw word.
__device__ __forceinline__ unsigned enc_pair(float v0, float v1) {
    unsigned lo  = (unsigned)__bfloat16_as_ushort(__float2bfloat16_rn(v0));
    unsigned u   = __float_as_uint(v1);
    unsigned s   = u & 0x80000000u;
    unsigned mag = u & 0x7fffffffu;
    int d = (int)(mag - lo + 0x8000u);
    unsigned tm = (d < 0) ? 0u : ((unsigned)d >> 16);
    if (tm > 0x7fffu) tm = 0x7fffu;
    return s | (tm << 16) | lo;
}

// ---------------- K1: CSR build + degree, float4 + warp scan -----------------
__global__ void k_build(const float* __restrict__ adj) {
    int warp = threadIdx.x >> 5;
    int lane = threadIdx.x & 31;
    int m = blockIdx.x * 8 + warp;
    const float4* row4 = (const float4*)(adj + (size_t)m * NN);
    int* cl = g_col + m * DCAP;
    int base = 0;
    for (int j0 = 0; j0 < NN; j0 += 128) {
        float4 v = row4[(j0 >> 2) + lane];
        unsigned nib = (v.x != 0.f ? 1u : 0u) | (v.y != 0.f ? 2u : 0u)
                     | (v.z != 0.f ? 4u : 0u) | (v.w != 0.f ? 8u : 0u);
        int c = __popc(nib);
        int sc = c;                       // inclusive scan over lanes
        #pragma unroll
        for (int o = 1; o < 32; o <<= 1) {
            int tv = __shfl_up_sync(0xffffffffu, sc, o);
            if (lane >= o) sc += tv;
        }
        int pos = base + sc - c;          // exclusive prefix
        int jb = j0 + 4 * lane;
        if (nib & 1u) { if (pos < DCAP) cl[pos] = jb;     pos++; }
        if (nib & 2u) { if (pos < DCAP) cl[pos] = jb + 1; pos++; }
        if (nib & 4u) { if (pos < DCAP) cl[pos] = jb + 2; pos++; }
        if (nib & 8u) { if (pos < DCAP) cl[pos] = jb + 3; pos++; }
        base += __shfl_sync(0xffffffffu, sc, 31);
    }
    if (lane == 0) {
        g_len[m]  = base < DCAP ? base : DCAP;
        g_dinv[m] = (base > 0) ? rsqrtf((float)base) : 0.f;  // degree == nnz
    }
}

// ---------------- K2: fused transpose + coef materialization -----------------
__global__ void k_prep(const float* __restrict__ x) {
    __shared__ float sm[32][193];
    if (blockIdx.x < 1024) {
        int n0 = (blockIdx.x & 255) * 16;
        int b  = blockIdx.x >> 8;
        for (int idx = threadIdx.x; idx < 32 * 192; idx += 256) {
            int c = idx / 192, r = idx % 192;   // r = n_local*12 + t
            sm[c][r] = x[(((size_t)(b * 32 + c)) * NN + n0) * TT + r];
        }
        __syncthreads();
        for (int idx = threadIdx.x; idx < 16 * 192; idx += 256) {
            int nl  = idx / 192;
            int rem = idx % 192;
            int t  = rem >> 4;
            int c2 = rem & 15;
            int r = nl * TT + t;
            float v0 = sm[2 * c2][r];
            float v1 = sm[2 * c2 + 1][r];
            size_t o = (size_t)(n0 + nl) * FF + (b * TT + t) * 32 + 2 * c2;
            *(float2*)(g_h + o) = make_float2(v0, v1);
            g_hb[o >> 1] = enc_pair(v0, v1);
        }
    } else {
        int idx = blockIdx.x - 1024;              // 0..2047
        int m   = idx * 2 + (threadIdx.x >> 7);   // half-block per row
        int tid = threadIdx.x & 127;
        int len = g_len[m];
        float dm = g_dinv[m];
        for (int i = tid; i < len; i += 128) {
            int j = g_col[m * DCAP + i];
            g_off[m * DCAP + i] = j * (FF * 2);
            g_cf [m * DCAP + i] = dm * g_dinv[j];
        }
    }
}

// ---- packed gather-accumulate: 8 features via 4 PRMT + 4 FFMA2 --------------
// even feature = prmt-shifted lo bf16 (exact); odd feature = raw word as fp32
// (lattice-rounded at encode time, error <= 2^-8 rel).
__device__ __forceinline__ void acc8x2(ull* A, uint4 v, ull cc) {
    asm volatile("{\n\t"
        ".reg .b32 lo;\n\t"
        ".reg .b64 vv;\n\t"
        "prmt.b32 lo, %1, 0, 0x1044;\n\t"
        "mov.b64 vv, {lo, %1};\n\t"
        "fma.rn.f32x2 %0, vv, %2, %0;\n\t"
        "}" : "+l"(A[0]) : "r"(v.x), "l"(cc));
    asm volatile("{\n\t"
        ".reg .b32 lo;\n\t"
        ".reg .b64 vv;\n\t"
        "prmt.b32 lo, %1, 0, 0x1044;\n\t"
        "mov.b64 vv, {lo, %1};\n\t"
        "fma.rn.f32x2 %0, vv, %2, %0;\n\t"
        "}" : "+l"(A[1]) : "r"(v.y), "l"(cc));
    asm volatile("{\n\t"
        ".reg .b32 lo;\n\t"
        ".reg .b64 vv;\n\t"
        "prmt.b32 lo, %1, 0, 0x1044;\n\t"
        "mov.b64 vv, {lo, %1};\n\t"
        "fma.rn.f32x2 %0, vv, %2, %0;\n\t"
        "}" : "+l"(A[2]) : "r"(v.z), "l"(cc));
    asm volatile("{\n\t"
        ".reg .b32 lo;\n\t"
        ".reg .b64 vv;\n\t"
        "prmt.b32 lo, %1, 0, 0x1044;\n\t"
        "mov.b64 vv, {lo, %1};\n\t"
        "fma.rn.f32x2 %0, vv, %2, %0;\n\t"
        "}" : "+l"(A[3]) : "r"(v.w), "l"(cc));
}

// ---- shared SpMM body: batch-of-4 loads, SoA smem entries -------------------
__device__ __forceinline__ void spmm_body(ull* A, const int* s_off,
                                          const float* s_cf, int len,
                                          const char* base) {
    int i = 0;
    for (; i + 4 <= len; i += 4) {
        int4   off = *(const int4*)  (s_off + i);   // one LDS.128: 4 offsets
        float4 cf  = *(const float4*)(s_cf  + i);   // one LDS.128: 4 coefs
        uint4 v0 = __ldg((const uint4*)(base + off.x));
        uint4 v1 = __ldg((const uint4*)(base + off.y));
        uint4 v2 = __ldg((const uint4*)(base + off.z));
        uint4 v3 = __ldg((const uint4*)(base + off.w));
        acc8x2(A, v0, fdup(cf.x));
        acc8x2(A, v1, fdup(cf.y));
        acc8x2(A, v2, fdup(cf.z));
        acc8x2(A, v3, fdup(cf.w));
    }
    for (; i < len; i++) {
        uint4 v = __ldg((const uint4*)(base + s_off[i]));
        acc8x2(A, v, fdup(s_cf[i]));
    }
}

// ---------------- K3: Tx1 = h - norm_adj * h (packed gather, f32x2 math) -----
__global__ void __launch_bounds__(192) k_spmm1() {
    int m   = blockIdx.x;
    int f0b = threadIdx.x * 16;            // byte offset of this thread's 8 feats
    __shared__ int   s_off[DCAP];
    __shared__ float s_cf [DCAP];
    int len = g_len[m];
    for (int i = threadIdx.x; i < len; i += 192) {
        s_off[i] = g_off[m * DCAP + i];
        s_cf [i] = g_cf [m * DCAP + i];
    }
    __syncthreads();

    ull A[4] = {0ull, 0ull, 0ull, 0ull};
    spmm_body(A, s_off, s_cf, len, (const char*)g_hb + f0b);

    float acc[8];
    funpack(A[0], acc[0], acc[1]);
    funpack(A[1], acc[2], acc[3]);
    funpack(A[2], acc[4], acc[5]);
    funpack(A[3], acc[6], acc[7]);

    size_t fbase = (size_t)m * FF + threadIdx.x * 8;
    float4 h0 = *(const float4*)(g_h + fbase);
    float4 h1 = *(const float4*)(g_h + fbase + 4);
    float r[8];
    r[0] = h0.x - acc[0]; r[1] = h0.y - acc[1];
    r[2] = h0.z - acc[2]; r[3] = h0.w - acc[3];
    r[4] = h1.x - acc[4]; r[5] = h1.y - acc[5];
    r[6] = h1.z - acc[6]; r[7] = h1.w - acc[7];
    *(float4*)(g_t1 + fbase)     = make_float4(r[0], r[1], r[2], r[3]);
    *(float4*)(g_t1 + fbase + 4) = make_float4(r[4], r[5], r[6], r[7]);
    uint4 o;
    o.x = enc_pair(r[0], r[1]);
    o.y = enc_pair(r[2], r[3]);
    o.z = enc_pair(r[4], r[5]);
    o.w = enc_pair(r[6], r[7]);
    *(uint4*)(g_t1b + (fbase >> 1)) = o;
}

// ---------------- K4: Tx2 = 2*(Tx1 - norm_adj*Tx1) - h -----------------------
__global__ void __launch_bounds__(192) k_spmm2() {
    int m   = blockIdx.x;
    int f0b = threadIdx.x * 16;
    __shared__ int   s_off[DCAP];
    __shared__ float s_cf [DCAP];
    int len = g_len[m];
    for (int i = threadIdx.x; i < len; i += 192) {
        s_off[i] = g_off[m * DCAP + i];
        s_cf [i] = g_cf [m * DCAP + i];
    }
    __syncthreads();

    ull A[4] = {0ull, 0ull, 0ull, 0ull};
    spmm_body(A, s_off, s_cf, len, (const char*)g_t1b + f0b);

    float acc[8];
    funpack(A[0], acc[0], acc[1]);
    funpack(A[1], acc[2], acc[3]);
    funpack(A[2], acc[4], acc[5]);
    funpack(A[3], acc[6], acc[7]);

    size_t fbase = (size_t)m * FF + threadIdx.x * 8;
    float4 t0 = *(const float4*)(g_t1 + fbase);
    float4 t1 = *(const float4*)(g_t1 + fbase + 4);
    float4 h0 = *(const float4*)(g_h  + fbase);
    float4 h1 = *(const float4*)(g_h  + fbase + 4);
    float4 r0, r1;
    r0.x = 2.f * (t0.x - acc[0]) - h0.x;
    r0.y = 2.f * (t0.y - acc[1]) - h0.y;
    r0.z = 2.f * (t0.z - acc[2]) - h0.z;
    r0.w = 2.f * (t0.w - acc[3]) - h0.w;
    r1.x = 2.f * (t1.x - acc[4]) - h1.x;
    r1.y = 2.f * (t1.y - acc[5]) - h1.y;
    r1.z = 2.f * (t1.z - acc[6]) - h1.z;
    r1.w = 2.f * (t1.w - acc[7]) - h1.w;
    *(float4*)(g_tx2 + fbase)     = r0;
    *(float4*)(g_tx2 + fbase + 4) = r1;
}

// ---------------- K5: out GEMM, 2 rows per thread (amortize weight LDS) ------
__global__ void __launch_bounds__(192) k_out(const float* __restrict__ w,
                                             const float* __restrict__ bias,
                                             float* __restrict__ out) {
    __shared__ float sW[3 * 32 * 32];   // [k][c][co]
    __shared__ float sB[32];
    for (int idx = threadIdx.x; idx < 3 * 32 * 32; idx += 192) sW[idx] = w[idx];
    if (threadIdx.x < 32) sB[threadIdx.x] = bias[threadIdx.x];
    __syncthreads();

    int b  = blockIdx.y;
    int p0 = threadIdx.x;          // row 0: (n,t) pair index
    int p1 = threadIdx.x + 192;    // row 1
    int n0b = blockIdx.x * 32;
    int na = n0b + p0 / 12, ta = p0 % 12;
    int nb = n0b + p1 / 12, tb = p1 % 12;

    size_t fba = (size_t)na * FF + (b * TT + ta) * 32;
    size_t fbb = (size_t)nb * FF + (b * TT + tb) * 32;

    ull Aa[16], Ab[16];            // 2 x 32 co accumulators as f32x2
    #pragma unroll
    for (int q = 0; q < 16; q++) {
        ull bq = fpack(sB[2*q], sB[2*q+1]);
        Aa[q] = bq; Ab[q] = bq;
    }

    #pragma unroll
    for (int c4 = 0; c4 < 8; c4++) {
        float4 Xa0 = __ldg((const float4*)(g_h   + fba + c4 * 4));
        float4 Xa1 = __ldg((const float4*)(g_t1  + fba + c4 * 4));
        float4 Xa2 = __ldg((const float4*)(g_tx2 + fba + c4 * 4));
        float4 Xb0 = __ldg((const float4*)(g_h   + fbb + c4 * 4));
        float4 Xb1 = __ldg((const float4*)(g_t1  + fbb + c4 * 4));
        float4 Xb2 = __ldg((const float4*)(g_tx2 + fbb + c4 * 4));
        #pragma unroll
        for (int cc = 0; cc < 4; cc++) {
            int c = c4 * 4 + cc;
            ull a0 = fdup(((const float*)&Xa0)[cc]);
            ull a1 = fdup(((const float*)&Xa1)[cc]);
            ull a2 = fdup(((const float*)&Xa2)[cc]);
            ull b0 = fdup(((const float*)&Xb0)[cc]);
            ull b1 = fdup(((const float*)&Xb1)[cc]);
            ull b2 = fdup(((const float*)&Xb2)[cc]);
            const ulonglong2* w0 = (const ulonglong2*)(sW +            c * 32);
            const ulonglong2* w1 = (const ulonglong2*)(sW + 32 * 32 +  c * 32);
            const ulonglong2* w2 = (const ulonglong2*)(sW + 2*32*32 +  c * 32);
            #pragma unroll
            for (int q = 0; q < 8; q++) {
                ulonglong2 W0 = w0[q], W1 = w1[q], W2 = w2[q];
                ffma2(Aa[2*q],   W0.x, a0); ffma2(Aa[2*q+1], W0.y, a0);
                ffma2(Aa[2*q],   W1.x, a1); ffma2(Aa[2*q+1], W1.y, a1);
                ffma2(Aa[2*q],   W2.x, a2); ffma2(Aa[2*q+1], W2.y, a2);
                ffma2(Ab[2*q],   W0.x, b0); ffma2(Ab[2*q+1], W0.y, b0);
                ffma2(Ab[2*q],   W1.x, b1); ffma2(Ab[2*q+1], W1.y, b1);
                ffma2(Ab[2*q],   W2.x, b2); ffma2(Ab[2*q+1], W2.y, b2);
            }
        }
    }
    float* poa = out + ((size_t)(b * 32) * NN + na) * TT + ta;
    float* pob = out + ((size_t)(b * 32) * NN + nb) * TT + tb;
    #pragma unroll
    for (int q = 0; q < 16; q++) {
        float x, y;
        funpack(Aa[q], x, y);
        poa[(size_t)(2*q)     * NN * TT] = x;
        poa[(size_t)(2*q + 1) * NN * TT] = y;
        funpack(Ab[q], x, y);
        pob[(size_t)(2*q)     * NN * TT] = x;
        pob[(size_t)(2*q + 1) * NN * TT] = y;
    }
}

// ---------------- launch -----------------------------------------------------
extern "C" void kernel_launch(void* const* d_in, const int* in_sizes, int n_in,
                              void* d_out, int out_size) {
    const float* x    = (const float*)d_in[0];   // [4,32,4096,12]
    const float* adj  = (const float*)d_in[1];   // [4096,4096]
    const float* w    = (const float*)d_in[2];   // [3,32,32]
    const float* bias = (const float*)d_in[3];   // [32]
    float* out = (float*)d_out;                  // [4,32,4096,12]

    k_build <<<NN / 8, 256>>>(adj);
    k_prep  <<<1024 + NN / 2, 256>>>(x);
    k_spmm1 <<<NN, 192>>>();
    k_spmm2 <<<NN, 192>>>();
    k_out   <<<dim3(NN / 32, BB), 192>>>(w, bias, out);
}

// round 14
// speedup vs baseline: 1.2406x; 1.0247x over previous
#include <cuda_runtime.h>
#include <cuda_bf16.h>
#include <cstddef>

// Problem constants
#define NN    4096          // nodes
#define BB    4             // batch
#define CC    32            // channels
#define TT    12            // time
#define FF    1536          // BT*C features per node
#define DCAP  256           // per-row neighbor capacity (max degree ~120)

typedef unsigned long long ull;

// ---------------- scratch (device globals; no allocations allowed) ----------
// Chebyshev via gather sums only:  s1 = A~*h,  s2 = A~*s1
//   Tx1 = h - s1 ;  Tx2 = h - 4 s1 + 2 s2
//   out = h(W0+W1+W2) - s1(W1+4W2) + s2(2W2) + bias
__device__ float g_dinv[NN];
__device__ int   g_len [NN];
__device__ int   g_col [NN * DCAP];
__device__ int   g_off [NN * DCAP];                // byte offsets (precomputed)
__device__ float g_cf  [NN * DCAP];                // coefficients (precomputed)
__device__ float         g_h [(size_t)NN * FF];    // fp32 master
__device__ float         g_s1[(size_t)NN * FF];    // A~*h
__device__ float         g_s2[(size_t)NN * FF];    // A~*s1
__device__ unsigned      g_hb [(size_t)NN * FF / 2];  // packed lattice-bf16 pairs
__device__ unsigned      g_s1b[(size_t)NN * FF / 2];

// ---- f32x2 helpers ----------------------------------------------------------
__device__ __forceinline__ ull fpack(float x, float y) {
    ull r; asm("mov.b64 %0, {%1, %2};" : "=l"(r) : "f"(x), "f"(y)); return r;
}
__device__ __forceinline__ ull fdup(float x) {
    ull r; asm("mov.b64 %0, {%1, %1};" : "=l"(r) : "f"(x)); return r;
}
__device__ __forceinline__ void funpack(ull a, float& x, float& y) {
    asm("mov.b64 {%0, %1}, %2;" : "=f"(x), "=f"(y) : "l"(a));
}
__device__ __forceinline__ void ffma2(ull& a, ull v, ull c) {
    asm("fma.rn.f32x2 %0, %1, %2, %0;" : "+l"(a) : "l"(v), "l"(c));
}

// ---- lattice pair encode -----------------------------------------------------
// word = (t<<16)|lo where lo = bf16_rn(v0) bits, t chosen so the whole word,
// read as fp32, is the nearest lattice point to v1 (error <= 2^-8 rel).
__device__ __forceinline__ unsigned enc_pair(float v0, float v1) {
    unsigned lo  = (unsigned)__bfloat16_as_ushort(__float2bfloat16_rn(v0));
    unsigned u   = __float_as_uint(v1);
    unsigned s   = u & 0x80000000u;
    unsigned mag = u & 0x7fffffffu;
    int d = (int)(mag - lo + 0x8000u);
    unsigned tm = (d < 0) ? 0u : ((unsigned)d >> 16);
    if (tm > 0x7fffu) tm = 0x7fffu;
    return s | (tm << 16) | lo;
}

// ---------------- K1: CSR build + degree, float4 + warp scan -----------------
__global__ void k_build(const float* __restrict__ adj) {
    int warp = threadIdx.x >> 5;
    int lane = threadIdx.x & 31;
    int m = blockIdx.x * 8 + warp;
    const float4* row4 = (const float4*)(adj + (size_t)m * NN);
    int* cl = g_col + m * DCAP;
    int base = 0;
    for (int j0 = 0; j0 < NN; j0 += 128) {
        float4 v = row4[(j0 >> 2) + lane];
        unsigned nib = (v.x != 0.f ? 1u : 0u) | (v.y != 0.f ? 2u : 0u)
                     | (v.z != 0.f ? 4u : 0u) | (v.w != 0.f ? 8u : 0u);
        int c = __popc(nib);
        int sc = c;                       // inclusive scan over lanes
        #pragma unroll
        for (int o = 1; o < 32; o <<= 1) {
            int tv = __shfl_up_sync(0xffffffffu, sc, o);
            if (lane >= o) sc += tv;
        }
        int pos = base + sc - c;          // exclusive prefix
        int jb = j0 + 4 * lane;
        if (nib & 1u) { if (pos < DCAP) cl[pos] = jb;     pos++; }
        if (nib & 2u) { if (pos < DCAP) cl[pos] = jb + 1; pos++; }
        if (nib & 4u) { if (pos < DCAP) cl[pos] = jb + 2; pos++; }
        if (nib & 8u) { if (pos < DCAP) cl[pos] = jb + 3; pos++; }
        base += __shfl_sync(0xffffffffu, sc, 31);
    }
    if (lane == 0) {
        g_len[m]  = base < DCAP ? base : DCAP;
        g_dinv[m] = (base > 0) ? rsqrtf((float)base) : 0.f;  // degree == nnz
    }
}

// ---------------- K2: fused transpose + coef materialization -----------------
__global__ void k_prep(const float* __restrict__ x) {
    __shared__ float sm[32][193];
    if (blockIdx.x < 1024) {
        int n0 = (blockIdx.x & 255) * 16;
        int b  = blockIdx.x >> 8;
        for (int idx = threadIdx.x; idx < 32 * 192; idx += 256) {
            int c = idx / 192, r = idx % 192;   // r = n_local*12 + t
            sm[c][r] = x[(((size_t)(b * 32 + c)) * NN + n0) * TT + r];
        }
        __syncthreads();
        for (int idx = threadIdx.x; idx < 16 * 192; idx += 256) {
            int nl  = idx / 192;
            int rem = idx % 192;
            int t  = rem >> 4;
            int c2 = rem & 15;
            int r = nl * TT + t;
            float v0 = sm[2 * c2][r];
            float v1 = sm[2 * c2 + 1][r];
            size_t o = (size_t)(n0 + nl) * FF + (b * TT + t) * 32 + 2 * c2;
            *(float2*)(g_h + o) = make_float2(v0, v1);
            g_hb[o >> 1] = enc_pair(v0, v1);
        }
    } else {
        int idx = blockIdx.x - 1024;              // 0..2047
        int m   = idx * 2 + (threadIdx.x >> 7);   // half-block per row
        int tid = threadIdx.x & 127;
        int len = g_len[m];
        float dm = g_dinv[m];
        for (int i = tid; i < len; i += 128) {
            int j = g_col[m * DCAP + i];
            g_off[m * DCAP + i] = j * (FF * 2);
            g_cf [m * DCAP + i] = dm * g_dinv[j];
        }
    }
}

// ---- packed gather-accumulate: 8 features via 4 PRMT + 4 FFMA2 --------------
__device__ __forceinline__ void acc8x2(ull* A, uint4 v, ull cc) {
    asm volatile("{\n\t"
        ".reg .b32 lo;\n\t"
        ".reg .b64 vv;\n\t"
        "prmt.b32 lo, %1, 0, 0x1044;\n\t"
        "mov.b64 vv, {lo, %1};\n\t"
        "fma.rn.f32x2 %0, vv, %2, %0;\n\t"
        "}" : "+l"(A[0]) : "r"(v.x), "l"(cc));
    asm volatile("{\n\t"
        ".reg .b32 lo;\n\t"
        ".reg .b64 vv;\n\t"
        "prmt.b32 lo, %1, 0, 0x1044;\n\t"
        "mov.b64 vv, {lo, %1};\n\t"
        "fma.rn.f32x2 %0, vv, %2, %0;\n\t"
        "}" : "+l"(A[1]) : "r"(v.y), "l"(cc));
    asm volatile("{\n\t"
        ".reg .b32 lo;\n\t"
        ".reg .b64 vv;\n\t"
        "prmt.b32 lo, %1, 0, 0x1044;\n\t"
        "mov.b64 vv, {lo, %1};\n\t"
        "fma.rn.f32x2 %0, vv, %2, %0;\n\t"
        "}" : "+l"(A[2]) : "r"(v.z), "l"(cc));
    asm volatile("{\n\t"
        ".reg .b32 lo;\n\t"
        ".reg .b64 vv;\n\t"
        "prmt.b32 lo, %1, 0, 0x1044;\n\t"
        "mov.b64 vv, {lo, %1};\n\t"
        "fma.rn.f32x2 %0, vv, %2, %0;\n\t"
        "}" : "+l"(A[3]) : "r"(v.w), "l"(cc));
}

// ---- shared SpMM body: batch-of-4 loads, SoA smem entries -------------------
__device__ __forceinline__ void spmm_body(ull* A, const int* s_off,
                                          const float* s_cf, int len,
                                          const char* base) {
    int i = 0;
    for (; i + 4 <= len; i += 4) {
        int4   off = *(const int4*)  (s_off + i);   // one LDS.128: 4 offsets
        float4 cf  = *(const float4*)(s_cf  + i);   // one LDS.128: 4 coefs
        uint4 v0 = __ldg((const uint4*)(base + off.x));
        uint4 v1 = __ldg((const uint4*)(base + off.y));
        uint4 v2 = __ldg((const uint4*)(base + off.z));
        uint4 v3 = __ldg((const uint4*)(base + off.w));
        acc8x2(A, v0, fdup(cf.x));
        acc8x2(A, v1, fdup(cf.y));
        acc8x2(A, v2, fdup(cf.z));
        acc8x2(A, v3, fdup(cf.w));
    }
    for (; i < len; i++) {
        uint4 v = __ldg((const uint4*)(base + s_off[i]));
        acc8x2(A, v, fdup(s_cf[i]));
    }
}

// ---------------- K3: s1 = norm_adj * h (packed gather, f32x2 math) ----------
__global__ void __launch_bounds__(192) k_spmm1() {
    int m   = blockIdx.x;
    int f0b = threadIdx.x * 16;            // byte offset of this thread's 8 feats
    __shared__ int   s_off[DCAP];
    __shared__ float s_cf [DCAP];
    int len = g_len[m];
    for (int i = threadIdx.x; i < len; i += 192) {
        s_off[i] = g_off[m * DCAP + i];
        s_cf [i] = g_cf [m * DCAP + i];
    }
    __syncthreads();

    ull A[4] = {0ull, 0ull, 0ull, 0ull};
    spmm_body(A, s_off, s_cf, len, (const char*)g_hb + f0b);

    float acc[8];
    funpack(A[0], acc[0], acc[1]);
    funpack(A[1], acc[2], acc[3]);
    funpack(A[2], acc[4], acc[5]);
    funpack(A[3], acc[6], acc[7]);

    size_t fbase = (size_t)m * FF + threadIdx.x * 8;
    *(float4*)(g_s1 + fbase)     = make_float4(acc[0], acc[1], acc[2], acc[3]);
    *(float4*)(g_s1 + fbase + 4) = make_float4(acc[4], acc[5], acc[6], acc[7]);
    uint4 o;
    o.x = enc_pair(acc[0], acc[1]);
    o.y = enc_pair(acc[2], acc[3]);
    o.z = enc_pair(acc[4], acc[5]);
    o.w = enc_pair(acc[6], acc[7]);
    *(uint4*)(g_s1b + (fbase >> 1)) = o;
}

// ---------------- K4: s2 = norm_adj * s1 -------------------------------------
__global__ void __launch_bounds__(192) k_spmm2() {
    int m   = blockIdx.x;
    int f0b = threadIdx.x * 16;
    __shared__ int   s_off[DCAP];
    __shared__ float s_cf [DCAP];
    int len = g_len[m];
    for (int i = threadIdx.x; i < len; i += 192) {
        s_off[i] = g_off[m * DCAP + i];
        s_cf [i] = g_cf [m * DCAP + i];
    }
    __syncthreads();

    ull A[4] = {0ull, 0ull, 0ull, 0ull};
    spmm_body(A, s_off, s_cf, len, (const char*)g_s1b + f0b);

    float acc[8];
    funpack(A[0], acc[0], acc[1]);
    funpack(A[1], acc[2], acc[3]);
    funpack(A[2], acc[4], acc[5]);
    funpack(A[3], acc[6], acc[7]);

    size_t fbase = (size_t)m * FF + threadIdx.x * 8;
    *(float4*)(g_s2 + fbase)     = make_float4(acc[0], acc[1], acc[2], acc[3]);
    *(float4*)(g_s2 + fbase + 4) = make_float4(acc[4], acc[5], acc[6], acc[7]);
}

// ---------------- K5: out = h*(W0+W1+W2) - s1*(W1+4W2) + s2*(2W2) + bias -----
__global__ void __launch_bounds__(192) k_out(const float* __restrict__ w,
                                             const float* __restrict__ bias,
                                             float* __restrict__ out) {
    __shared__ float sW[3 * 32 * 32];   // transformed weights [k][c][co]
    __shared__ float sB[32];
    for (int idx = threadIdx.x; idx < 1024; idx += 192) {
        float w0 = w[idx], w1 = w[1024 + idx], w2 = w[2048 + idx];
        sW[idx]        = w0 + w1 + w2;
        sW[1024 + idx] = -(w1 + 4.f * w2);
        sW[2048 + idx] = 2.f * w2;
    }
    if (threadIdx.x < 32) sB[threadIdx.x] = bias[threadIdx.x];
    __syncthreads();

    int b  = blockIdx.y;
    int p0 = threadIdx.x;          // row 0: (n,t) pair index
    int p1 = threadIdx.x + 192;    // row 1
    int n0b = blockIdx.x * 32;
    int na = n0b + p0 / 12, ta = p0 % 12;
    int nb = n0b + p1 / 12, tb = p1 % 12;

    size_t fba = (size_t)na * FF + (b * TT + ta) * 32;
    size_t fbb = (size_t)nb * FF + (b * TT + tb) * 32;

    ull Aa[16], Ab[16];            // 2 x 32 co accumulators as f32x2
    #pragma unroll
    for (int q = 0; q < 16; q++) {
        ull bq = fpack(sB[2*q], sB[2*q+1]);
        Aa[q] = bq; Ab[q] = bq;
    }

    #pragma unroll
    for (int c4 = 0; c4 < 8; c4++) {
        float4 Xa0 = __ldg((const float4*)(g_h  + fba + c4 * 4));
        float4 Xa1 = __ldg((const float4*)(g_s1 + fba + c4 * 4));
        float4 Xa2 = __ldg((const float4*)(g_s2 + fba + c4 * 4));
        float4 Xb0 = __ldg((const float4*)(g_h  + fbb + c4 * 4));
        float4 Xb1 = __ldg((const float4*)(g_s1 + fbb + c4 * 4));
        float4 Xb2 = __ldg((const float4*)(g_s2 + fbb + c4 * 4));
        #pragma unroll
        for (int cc = 0; cc < 4; cc++) {
            int c = c4 * 4 + cc;
            ull a0 = fdup(((const float*)&Xa0)[cc]);
            ull a1 = fdup(((const float*)&Xa1)[cc]);
            ull a2 = fdup(((const float*)&Xa2)[cc]);
            ull b0 = fdup(((const float*)&Xb0)[cc]);
            ull b1 = fdup(((const float*)&Xb1)[cc]);
            ull b2 = fdup(((const float*)&Xb2)[cc]);
            const ulonglong2* w0 = (const ulonglong2*)(sW +            c * 32);
            const ulonglong2* w1 = (const ulonglong2*)(sW + 32 * 32 +  c * 32);
            const ulonglong2* w2 = (const ulonglong2*)(sW + 2*32*32 +  c * 32);
            #pragma unroll
            for (int q = 0; q < 8; q++) {
                ulonglong2 W0 = w0[q], W1 = w1[q], W2 = w2[q];
                ffma2(Aa[2*q],   W0.x, a0); ffma2(Aa[2*q+1], W0.y, a0);
                ffma2(Aa[2*q],   W1.x, a1); ffma2(Aa[2*q+1], W1.y, a1);
                ffma2(Aa[2*q],   W2.x, a2); ffma2(Aa[2*q+1], W2.y, a2);
                ffma2(Ab[2*q],   W0.x, b0); ffma2(Ab[2*q+1], W0.y, b0);
                ffma2(Ab[2*q],   W1.x, b1); ffma2(Ab[2*q+1], W1.y, b1);
                ffma2(Ab[2*q],   W2.x, b2); ffma2(Ab[2*q+1], W2.y, b2);
            }
        }
    }
    float* poa = out + ((size_t)(b * 32) * NN + na) * TT + ta;
    float* pob = out + ((size_t)(b * 32) * NN + nb) * TT + tb;
    #pragma unroll
    for (int q = 0; q < 16; q++) {
        float x, y;
        funpack(Aa[q], x, y);
        poa[(size_t)(2*q)     * NN * TT] = x;
        poa[(size_t)(2*q + 1) * NN * TT] = y;
        funpack(Ab[q], x, y);
        pob[(size_t)(2*q)     * NN * TT] = x;
        pob[(size_t)(2*q + 1) * NN * TT] = y;
    }
}

// ---------------- launch -----------------------------------------------------
extern "C" void kernel_launch(void* const* d_in, const int* in_sizes, int n_in,
                              void* d_out, int out_size) {
    const float* x    = (const float*)d_in[0];   // [4,32,4096,12]
    const float* adj  = (const float*)d_in[1];   // [4096,4096]
    const float* w    = (const float*)d_in[2];   // [3,32,32]
    const float* bias = (const float*)d_in[3];   // [32]
    float* out = (float*)d_out;                  // [4,32,4096,12]

    k_build <<<NN / 8, 256>>>(adj);
    k_prep  <<<1024 + NN / 2, 256>>>(x);
    k_spmm1 <<<NN, 192>>>();
    k_spmm2 <<<NN, 192>>>();
    k_out   <<<dim3(NN / 32, BB), 192>>>(w, bias, out);
}

// round 15
// speedup vs baseline: 1.2830x; 1.0342x over previous
#include <cuda_runtime.h>
#include <cuda_bf16.h>
#include <cstddef>

// Problem constants
#define NN    4096          // nodes
#define BB    4             // batch
#define CC    32            // channels
#define TT    12            // time
#define FF    1536          // BT*C features per node
#define DCAP  256           // per-row neighbor capacity (max degree ~120)

typedef unsigned long long ull;

// ---------------- scratch (device globals; no allocations allowed) ----------
// Chebyshev via gather sums only:  s1 = A~*h,  s2 = A~*s1
//   out = h(W0+W1+W2) - s1(W1+4W2) + s2(2W2) + bias
__device__ float g_dinv[NN];
__device__ int   g_len [NN];
__device__ int   g_col [NN * DCAP];
__device__ float         g_h [(size_t)NN * FF];    // fp32 master
__device__ float         g_s1[(size_t)NN * FF];    // A~*h
__device__ float         g_s2[(size_t)NN * FF];    // A~*s1
__device__ unsigned      g_hb [(size_t)NN * FF / 2];  // packed lattice-bf16 pairs
__device__ unsigned      g_s1b[(size_t)NN * FF / 2];

// ---- f32x2 helpers ----------------------------------------------------------
__device__ __forceinline__ ull fpack(float x, float y) {
    ull r; asm("mov.b64 %0, {%1, %2};" : "=l"(r) : "f"(x), "f"(y)); return r;
}
__device__ __forceinline__ ull fdup(float x) {
    ull r; asm("mov.b64 %0, {%1, %1};" : "=l"(r) : "f"(x)); return r;
}
__device__ __forceinline__ void funpack(ull a, float& x, float& y) {
    asm("mov.b64 {%0, %1}, %2;" : "=f"(x), "=f"(y) : "l"(a));
}
__device__ __forceinline__ void ffma2(ull& a, ull v, ull c) {
    asm("fma.rn.f32x2 %0, %1, %2, %0;" : "+l"(a) : "l"(v), "l"(c));
}

// ---- lattice pair encode -----------------------------------------------------
// word = (t<<16)|lo where lo = bf16_rn(v0) bits, t chosen so the whole word,
// read as fp32, is the nearest lattice point to v1 (error <= 2^-8 rel).
__device__ __forceinline__ unsigned enc_pair(float v0, float v1) {
    unsigned lo  = (unsigned)__bfloat16_as_ushort(__float2bfloat16_rn(v0));
    unsigned u   = __float_as_uint(v1);
    unsigned s   = u & 0x80000000u;
    unsigned mag = u & 0x7fffffffu;
    int d = (int)(mag - lo + 0x8000u);
    unsigned tm = (d < 0) ? 0u : ((unsigned)d >> 16);
    if (tm > 0x7fffu) tm = 0x7fffu;
    return s | (tm << 16) | lo;
}

// ---------------- K1: fused CSR build + transpose (independent halves) -------
// blocks [0, 512):     build — 8 warps, one adjacency row each
// blocks [512, 1536):  transpose x[B,C,N,T] -> h[n][f] (fp32 + packed shadow)
__global__ void k_pre(const float* __restrict__ adj,
                      const float* __restrict__ x) {
    __shared__ float sm[32][193];
    if (blockIdx.x < 512) {
        int warp = threadIdx.x >> 5;
        int lane = threadIdx.x & 31;
        int m = blockIdx.x * 8 + warp;
        const float4* row4 = (const float4*)(adj + (size_t)m * NN);
        int* cl = g_col + m * DCAP;
        int base = 0;
        for (int j0 = 0; j0 < NN; j0 += 128) {
            float4 v = row4[(j0 >> 2) + lane];
            unsigned nib = (v.x != 0.f ? 1u : 0u) | (v.y != 0.f ? 2u : 0u)
                         | (v.z != 0.f ? 4u : 0u) | (v.w != 0.f ? 8u : 0u);
            int c = __popc(nib);
            int sc = c;                       // inclusive scan over lanes
            #pragma unroll
            for (int o = 1; o < 32; o <<= 1) {
                int tv = __shfl_up_sync(0xffffffffu, sc, o);
                if (lane >= o) sc += tv;
            }
            int pos = base + sc - c;          // exclusive prefix
            int jb = j0 + 4 * lane;
            if (nib & 1u) { if (pos < DCAP) cl[pos] = jb;     pos++; }
            if (nib & 2u) { if (pos < DCAP) cl[pos] = jb + 1; pos++; }
            if (nib & 4u) { if (pos < DCAP) cl[pos] = jb + 2; pos++; }
            if (nib & 8u) { if (pos < DCAP) cl[pos] = jb + 3; pos++; }
            base += __shfl_sync(0xffffffffu, sc, 31);
        }
        if (lane == 0) {
            g_len[m]  = base < DCAP ? base : DCAP;
            g_dinv[m] = (base > 0) ? rsqrtf((float)base) : 0.f;  // deg == nnz
        }
    } else {
        int tb = blockIdx.x - 512;            // 0..1023
        int n0 = (tb & 255) * 16;
        int b  = tb >> 8;
        for (int idx = threadIdx.x; idx < 32 * 192; idx += 256) {
            int c = idx / 192, r = idx % 192;   // r = n_local*12 + t
            sm[c][r] = x[(((size_t)(b * 32 + c)) * NN + n0) * TT + r];
        }
        __syncthreads();
        for (int idx = threadIdx.x; idx < 16 * 192; idx += 256) {
            int nl  = idx / 192;
            int rem = idx % 192;
            int t  = rem >> 4;
            int c2 = rem & 15;
            int r = nl * TT + t;
            float v0 = sm[2 * c2][r];
            float v1 = sm[2 * c2 + 1][r];
            size_t o = (size_t)(n0 + nl) * FF + (b * TT + t) * 32 + 2 * c2;
            *(float2*)(g_h + o) = make_float2(v0, v1);
            g_hb[o >> 1] = enc_pair(v0, v1);
        }
    }
}

// ---- packed gather-accumulate: 8 features via 4 PRMT + 4 FFMA2 --------------
__device__ __forceinline__ void acc8x2(ull* A, uint4 v, ull cc) {
    asm volatile("{\n\t"
        ".reg .b32 lo;\n\t"
        ".reg .b64 vv;\n\t"
        "prmt.b32 lo, %1, 0, 0x1044;\n\t"
        "mov.b64 vv, {lo, %1};\n\t"
        "fma.rn.f32x2 %0, vv, %2, %0;\n\t"
        "}" : "+l"(A[0]) : "r"(v.x), "l"(cc));
    asm volatile("{\n\t"
        ".reg .b32 lo;\n\t"
        ".reg .b64 vv;\n\t"
        "prmt.b32 lo, %1, 0, 0x1044;\n\t"
        "mov.b64 vv, {lo, %1};\n\t"
        "fma.rn.f32x2 %0, vv, %2, %0;\n\t"
        "}" : "+l"(A[1]) : "r"(v.y), "l"(cc));
    asm volatile("{\n\t"
        ".reg .b32 lo;\n\t"
        ".reg .b64 vv;\n\t"
        "prmt.b32 lo, %1, 0, 0x1044;\n\t"
        "mov.b64 vv, {lo, %1};\n\t"
        "fma.rn.f32x2 %0, vv, %2, %0;\n\t"
        "}" : "+l"(A[2]) : "r"(v.z), "l"(cc));
    asm volatile("{\n\t"
        ".reg .b32 lo;\n\t"
        ".reg .b64 vv;\n\t"
        "prmt.b32 lo, %1, 0, 0x1044;\n\t"
        "mov.b64 vv, {lo, %1};\n\t"
        "fma.rn.f32x2 %0, vv, %2, %0;\n\t"
        "}" : "+l"(A[3]) : "r"(v.w), "l"(cc));
}

// ---- shared SpMM body: batch-of-4 loads, SoA smem entries -------------------
__device__ __forceinline__ void spmm_body(ull* A, const int* s_off,
                                          const float* s_cf, int len,
                                          const char* base) {
    int i = 0;
    for (; i + 4 <= len; i += 4) {
        int4   off = *(const int4*)  (s_off + i);   // one LDS.128: 4 offsets
        float4 cf  = *(const float4*)(s_cf  + i);   // one LDS.128: 4 coefs
        uint4 v0 = __ldg((const uint4*)(base + off.x));
        uint4 v1 = __ldg((const uint4*)(base + off.y));
        uint4 v2 = __ldg((const uint4*)(base + off.z));
        uint4 v3 = __ldg((const uint4*)(base + off.w));
        acc8x2(A, v0, fdup(cf.x));
        acc8x2(A, v1, fdup(cf.y));
        acc8x2(A, v2, fdup(cf.z));
        acc8x2(A, v3, fdup(cf.w));
    }
    for (; i < len; i++) {
        uint4 v = __ldg((const uint4*)(base + s_off[i]));
        acc8x2(A, v, fdup(s_cf[i]));
    }
}

// ---- shared prologue: stage SoA entries, computing coef inline --------------
__device__ __forceinline__ int stage_entries(int m, int* s_off, float* s_cf) {
    int len = g_len[m];
    float dm = g_dinv[m];
    for (int i = threadIdx.x; i < len; i += 192) {
        int j = g_col[m * DCAP + i];
        s_off[i] = j * (FF * 2);
        s_cf [i] = dm * g_dinv[j];
    }
    __syncthreads();
    return len;
}

// ---------------- K2: s1 = norm_adj * h (packed gather, f32x2 math) ----------
__global__ void __launch_bounds__(192) k_spmm1() {
    int m   = blockIdx.x;
    int f0b = threadIdx.x * 16;            // byte offset of this thread's 8 feats
    __shared__ int   s_off[DCAP];
    __shared__ float s_cf [DCAP];
    int len = stage_entries(m, s_off, s_cf);

    ull A[4] = {0ull, 0ull, 0ull, 0ull};
    spmm_body(A, s_off, s_cf, len, (const char*)g_hb + f0b);

    float acc[8];
    funpack(A[0], acc[0], acc[1]);
    funpack(A[1], acc[2], acc[3]);
    funpack(A[2], acc[4], acc[5]);
    funpack(A[3], acc[6], acc[7]);

    size_t fbase = (size_t)m * FF + threadIdx.x * 8;
    *(float4*)(g_s1 + fbase)     = make_float4(acc[0], acc[1], acc[2], acc[3]);
    *(float4*)(g_s1 + fbase + 4) = make_float4(acc[4], acc[5], acc[6], acc[7]);
    uint4 o;
    o.x = enc_pair(acc[0], acc[1]);
    o.y = enc_pair(acc[2], acc[3]);
    o.z = enc_pair(acc[4], acc[5]);
    o.w = enc_pair(acc[6], acc[7]);
    *(uint4*)(g_s1b + (fbase >> 1)) = o;
}

// ---------------- K3: s2 = norm_adj * s1 -------------------------------------
__global__ void __launch_bounds__(192) k_spmm2() {
    int m   = blockIdx.x;
    int f0b = threadIdx.x * 16;
    __shared__ int   s_off[DCAP];
    __shared__ float s_cf [DCAP];
    int len = stage_entries(m, s_off, s_cf);

    ull A[4] = {0ull, 0ull, 0ull, 0ull};
    spmm_body(A, s_off, s_cf, len, (const char*)g_s1b + f0b);

    float acc[8];
    funpack(A[0], acc[0], acc[1]);
    funpack(A[1], acc[2], acc[3]);
    funpack(A[2], acc[4], acc[5]);
    funpack(A[3], acc[6], acc[7]);

    size_t fbase = (size_t)m * FF + threadIdx.x * 8;
    *(float4*)(g_s2 + fbase)     = make_float4(acc[0], acc[1], acc[2], acc[3]);
    *(float4*)(g_s2 + fbase + 4) = make_float4(acc[4], acc[5], acc[6], acc[7]);
}

// ---------------- K4: out = h*(W0+W1+W2) - s1*(W1+4W2) + s2*(2W2) + bias -----
__global__ void __launch_bounds__(192) k_out(const float* __restrict__ w,
                                             const float* __restrict__ bias,
                                             float* __restrict__ out) {
    __shared__ float sW[3 * 32 * 32];   // transformed weights [k][c][co]
    __shared__ float sB[32];
    for (int idx = threadIdx.x; idx < 1024; idx += 192) {
        float w0 = w[idx], w1 = w[1024 + idx], w2 = w[2048 + idx];
        sW[idx]        = w0 + w1 + w2;
        sW[1024 + idx] = -(w1 + 4.f * w2);
        sW[2048 + idx] = 2.f * w2;
    }
    if (threadIdx.x < 32) sB[threadIdx.x] = bias[threadIdx.x];
    __syncthreads();

    int b  = blockIdx.y;
    int p0 = threadIdx.x;          // row 0: (n,t) pair index
    int p1 = threadIdx.x + 192;    // row 1
    int n0b = blockIdx.x * 32;
    int na = n0b + p0 / 12, ta = p0 % 12;
    int nb = n0b + p1 / 12, tb = p1 % 12;

    size_t fba = (size_t)na * FF + (b * TT + ta) * 32;
    size_t fbb = (size_t)nb * FF + (b * TT + tb) * 32;

    ull Aa[16], Ab[16];            // 2 x 32 co accumulators as f32x2
    #pragma unroll
    for (int q = 0; q < 16; q++) {
        ull bq = fpack(sB[2*q], sB[2*q+1]);
        Aa[q] = bq; Ab[q] = bq;
    }

    #pragma unroll
    for (int c4 = 0; c4 < 8; c4++) {
        float4 Xa0 = __ldg((const float4*)(g_h  + fba + c4 * 4));
        float4 Xa1 = __ldg((const float4*)(g_s1 + fba + c4 * 4));
        float4 Xa2 = __ldg((const float4*)(g_s2 + fba + c4 * 4));
        float4 Xb0 = __ldg((const float4*)(g_h  + fbb + c4 * 4));
        float4 Xb1 = __ldg((const float4*)(g_s1 + fbb + c4 * 4));
        float4 Xb2 = __ldg((const float4*)(g_s2 + fbb + c4 * 4));
        #pragma unroll
        for (int cc = 0; cc < 4; cc++) {
            int c = c4 * 4 + cc;
            ull a0 = fdup(((const float*)&Xa0)[cc]);
            ull a1 = fdup(((const float*)&Xa1)[cc]);
            ull a2 = fdup(((const float*)&Xa2)[cc]);
            ull b0 = fdup(((const float*)&Xb0)[cc]);
            ull b1 = fdup(((const float*)&Xb1)[cc]);
            ull b2 = fdup(((const float*)&Xb2)[cc]);
            const ulonglong2* w0 = (const ulonglong2*)(sW +            c * 32);
            const ulonglong2* w1 = (const ulonglong2*)(sW + 32 * 32 +  c * 32);
            const ulonglong2* w2 = (const ulonglong2*)(sW + 2*32*32 +  c * 32);
            #pragma unroll
            for (int q = 0; q < 8; q++) {
                ulonglong2 W0 = w0[q], W1 = w1[q], W2 = w2[q];
                ffma2(Aa[2*q],   W0.x, a0); ffma2(Aa[2*q+1], W0.y, a0);
                ffma2(Aa[2*q],   W1.x, a1); ffma2(Aa[2*q+1], W1.y, a1);
                ffma2(Aa[2*q],   W2.x, a2); ffma2(Aa[2*q+1], W2.y, a2);
                ffma2(Ab[2*q],   W0.x, b0); ffma2(Ab[2*q+1], W0.y, b0);
                ffma2(Ab[2*q],   W1.x, b1); ffma2(Ab[2*q+1], W1.y, b1);
                ffma2(Ab[2*q],   W2.x, b2); ffma2(Ab[2*q+1], W2.y, b2);
            }
        }
    }
    float* poa = out + ((size_t)(b * 32) * NN + na) * TT + ta;
    float* pob = out + ((size_t)(b * 32) * NN + nb) * TT + tb;
    #pragma unroll
    for (int q = 0; q < 16; q++) {
        float x, y;
        funpack(Aa[q], x, y);
        poa[(size_t)(2*q)     * NN * TT] = x;
        poa[(size_t)(2*q + 1) * NN * TT] = y;
        funpack(Ab[q], x, y);
        pob[(size_t)(2*q)     * NN * TT] = x;
        pob[(size_t)(2*q + 1) * NN * TT] = y;
    }
}

// ---------------- launch -----------------------------------------------------
extern "C" void kernel_launch(void* const* d_in, const int* in_sizes, int n_in,
                              void* d_out, int out_size) {
    const float* x    = (const float*)d_in[0];   // [4,32,4096,12]
    const float* adj  = (const float*)d_in[1];   // [4096,4096]
    const float* w    = (const float*)d_in[2];   // [3,32,32]
    const float* bias = (const float*)d_in[3];   // [32]
    float* out = (float*)d_out;                  // [4,32,4096,12]

    k_pre   <<<1536, 256>>>(adj, x);
    k_spmm1 <<<NN, 192>>>();
    k_spmm2 <<<NN, 192>>>();
    k_out   <<<dim3(NN / 32, BB), 192>>>(w, bias, out);
}